// round 14
// baseline (speedup 1.0000x reference)
#include <cuda_runtime.h>
#include <cuda_bf16.h>

// DepthwiseRREUp: x [B=8, C=256, G=4, H=64, W=64] fp32, dw [C,1,2,2] fp32.
// out [B, C, G, 128, 128]:
//   out[b,c,g,2i+di,2j+dj] = x[b,c,g,i,j] * f(c,g)[di,dj],  f = rot90(dw[c], k=g) CCW.
//
// dw[c] = [[a,b],[c,d]]:
//   g=0: (a,b,c,d)  g=1: (b,d,a,c)  g=2: (d,c,b,a)  g=3: (c,a,d,b)
// Branch-free permutation: g&2 = double rotation (reverse), g&1 = single
// rotation (f00,f01,f10,f11) <- (f01,f11,f00,f10).
//
// R14: 256-bit stores. sm_103a supports st.global.v8.f32 (Blackwell 256-bit
// STG; confirmed by this toolchain's ptxas diagnostics). One thread per input
// FLOAT4 -> 8 consecutive output floats per row (32B, v8-aligned) x 2 rows =
// two STG.256, lanes fully contiguous (1024B/warp/instr). Halves store
// instruction and L2-request count on the write path vs STG.128.

#define OUT_PLANE_F4 4096            // 128*128/4
#define OUT_ROW_F4   32              // 128/4

__device__ __forceinline__ void stg256(float4* p, float4 a, float4 b) {
    asm volatile("st.global.v8.f32 [%0], {%1,%2,%3,%4,%5,%6,%7,%8};"
        :: "l"(p),
           "f"(a.x), "f"(a.y), "f"(a.z), "f"(a.w),
           "f"(b.x), "f"(b.y), "f"(b.z), "f"(b.w)
        : "memory");
}

__global__ __launch_bounds__(512)
void rre_up_kernel(const float4* __restrict__ x4,
                   const float4* __restrict__ dw4,   // [C] float4 = (a,b,c,d)
                   float4* __restrict__ out)
{
    int idx = blockIdx.x * blockDim.x + threadIdx.x;   // exact grid, no tail

    int plane = idx >> 10;           // (b*C + c)*G + g, 0..8191 (1024 float4/plane)
    int p     = idx & 1023;          // within-plane float4 index
    int i     = p >> 4;              // input row 0..63
    int j4    = p & 15;              // input float4 col 0..15

    int cg = plane & 1023;           // c*4 + g
    int c  = cg >> 2;
    int g  = cg & 3;

    float4 w = __ldg(&dw4[c]);       // warp-uniform broadcast, 4 KB total

    // Branch-free rot90 permutation.
    float t00 = w.x, t01 = w.y, t10 = w.z, t11 = w.w;
    if (g & 2) { float a = t00, b = t01;
                 t00 = t11; t01 = t10; t10 = b; t11 = a; }
    float f00 = t00, f01 = t01, f10 = t10, f11 = t11;
    if (g & 1) { f00 = t01; f01 = t11; f10 = t00; f11 = t10; }

    float4 v = __ldcs(&x4[idx]);     // streamed LDG.128, no reuse

    // Output base: row 2i, cols 8*j4 .. 8*j4+7  (32B-aligned for v8)
    float4* o = out + (size_t)plane * OUT_PLANE_F4
                    + (size_t)(2 * i) * OUT_ROW_F4
                    + 2 * j4;

    float4 r0a = make_float4(v.x * f00, v.x * f01, v.y * f00, v.y * f01);
    float4 r0b = make_float4(v.z * f00, v.z * f01, v.w * f00, v.w * f01);
    float4 r1a = make_float4(v.x * f10, v.x * f11, v.y * f10, v.y * f11);
    float4 r1b = make_float4(v.z * f10, v.z * f11, v.w * f10, v.w * f11);

    stg256(&o[0],          r0a, r0b);   // row 2i,   256-bit store
    stg256(&o[OUT_ROW_F4], r1a, r1b);   // row 2i+1, 256-bit store
}

extern "C" void kernel_launch(void* const* d_in, const int* in_sizes, int n_in,
                              void* d_out, int out_size)
{
    const float4* x4  = (const float4*)d_in[0];   // [8,256,4,64,64] f32
    const float4* dw4 = (const float4*)d_in[1];   // [256,1,2,2] f32
    float4* out       = (float4*)d_out;           // [8,256,4,128,128] f32

    int n4 = in_sizes[0] / 4;                     // 8,388,608 float4 (pow2: exact grid)
    int block = 512;
    int grid  = n4 / block;                       // 16384
    rre_up_kernel<<<grid, block>>>(x4, dw4, out);
}

// round 16
// speedup vs baseline: 1.0035x; 1.0035x over previous
#include <cuda_runtime.h>
#include <cuda_bf16.h>

// DepthwiseRREUp: x [B=8, C=256, G=4, H=64, W=64] fp32, dw [C,1,2,2] fp32.
// out [B, C, G, 128, 128]:
//   out[b,c,g,2i+di,2j+dj] = x[b,c,g,i,j] * f(c,g)[di,dj],  f = rot90(dw[c], k=g) CCW.
//
// dw[c] = [[a,b],[c,d]]:
//   g=0: (a,b,c,d)  g=1: (b,d,a,c)  g=2: (d,c,b,a)  g=3: (c,a,d,b)
// Branch-free permutation: g&2 = double rotation (reverse), g&1 = single
// rotation (f00,f01,f10,f11) <- (f01,f11,f00,f10).
//
// R15: fully 256-bit streaming. One thread per 8 input floats (one LDG.256),
// producing 16 consecutive output floats per row x 2 rows = 4 STG.256
// (write-through, best-measured policy). All accesses lane-contiguous and
// 32B-aligned. Minimal LSU issue count: 5 memory instrs per 96B-in/384B-out.

#define OUT_PLANE_F4 4096            // 128*128/4
#define OUT_ROW_F4   32              // 128/4

struct f8 { float4 a, b; };

__device__ __forceinline__ f8 ldg256_cs(const float4* p) {
    f8 v;
    asm("ld.global.nc.cs.v8.f32 {%0,%1,%2,%3,%4,%5,%6,%7}, [%8];"
        : "=f"(v.a.x), "=f"(v.a.y), "=f"(v.a.z), "=f"(v.a.w),
          "=f"(v.b.x), "=f"(v.b.y), "=f"(v.b.z), "=f"(v.b.w)
        : "l"(p));
    return v;
}

__device__ __forceinline__ void stg256_wt(float4* p, float4 a, float4 b) {
    asm volatile("st.global.wt.v8.f32 [%0], {%1,%2,%3,%4,%5,%6,%7,%8};"
        :: "l"(p),
           "f"(a.x), "f"(a.y), "f"(a.z), "f"(a.w),
           "f"(b.x), "f"(b.y), "f"(b.z), "f"(b.w)
        : "memory");
}

__global__ __launch_bounds__(512)
void rre_up_kernel(const float4* __restrict__ x4,
                   const float4* __restrict__ dw4,   // [C] float4 = (a,b,c,d)
                   float4* __restrict__ out)
{
    int idx = blockIdx.x * blockDim.x + threadIdx.x;  // exact grid, no tail
    // one thread per 8 input floats = 2 float4 = quarter input row

    int plane = idx >> 9;            // (b*C + c)*G + g, 0..8191 (512 v8/plane)
    int p     = idx & 511;           // within-plane v8 index
    int i     = p >> 3;              // input row 0..63
    int j8    = p & 7;               // v8 col 0..7 (8 floats each)

    int cg = plane & 1023;           // c*4 + g
    int c  = cg >> 2;
    int g  = cg & 3;

    float4 w = __ldg(&dw4[c]);       // warp-uniform broadcast, 4 KB total

    // Branch-free rot90 permutation.
    float t00 = w.x, t01 = w.y, t10 = w.z, t11 = w.w;
    if (g & 2) { float a = t00, b = t01;
                 t00 = t11; t01 = t10; t10 = b; t11 = a; }
    float f00 = t00, f01 = t01, f10 = t10, f11 = t11;
    if (g & 1) { f00 = t01; f01 = t11; f10 = t00; f11 = t10; }

    f8 v = ldg256_cs(&x4[2 * idx]);  // 8 input floats, streamed

    // Output base: row 2i, cols 16*j8 .. 16*j8+15
    float4* o = out + (size_t)plane * OUT_PLANE_F4
                    + (size_t)(2 * i) * OUT_ROW_F4
                    + 4 * j8;

    // Row 2i (top filter row f00,f01), 16 floats = 2 x v8
    float4 r0a = make_float4(v.a.x * f00, v.a.x * f01, v.a.y * f00, v.a.y * f01);
    float4 r0b = make_float4(v.a.z * f00, v.a.z * f01, v.a.w * f00, v.a.w * f01);
    float4 r0c = make_float4(v.b.x * f00, v.b.x * f01, v.b.y * f00, v.b.y * f01);
    float4 r0d = make_float4(v.b.z * f00, v.b.z * f01, v.b.w * f00, v.b.w * f01);
    // Row 2i+1 (bottom filter row f10,f11)
    float4 r1a = make_float4(v.a.x * f10, v.a.x * f11, v.a.y * f10, v.a.y * f11);
    float4 r1b = make_float4(v.a.z * f10, v.a.z * f11, v.a.w * f10, v.a.w * f11);
    float4 r1c = make_float4(v.b.x * f10, v.b.x * f11, v.b.y * f10, v.b.y * f11);
    float4 r1d = make_float4(v.b.z * f10, v.b.z * f11, v.b.w * f10, v.b.w * f11);

    stg256_wt(&o[0],              r0a, r0b);
    stg256_wt(&o[2],              r0c, r0d);
    stg256_wt(&o[OUT_ROW_F4],     r1a, r1b);
    stg256_wt(&o[OUT_ROW_F4 + 2], r1c, r1d);
}

extern "C" void kernel_launch(void* const* d_in, const int* in_sizes, int n_in,
                              void* d_out, int out_size)
{
    const float4* x4  = (const float4*)d_in[0];   // [8,256,4,64,64] f32
    const float4* dw4 = (const float4*)d_in[1];   // [256,1,2,2] f32
    float4* out       = (float4*)d_out;           // [8,256,4,128,128] f32

    int n8 = in_sizes[0] / 8;                     // 4,194,304 v8 units (pow2: exact grid)
    int block = 512;
    int grid  = n8 / block;                       // 8192
    rre_up_kernel<<<grid, block>>>(x4, dw4, out);
}